// round 1
// baseline (speedup 1.0000x reference)
#include <cuda_runtime.h>
#include <cstdint>

#define BATCH 16
#define NCLS 7
#define HH 368
#define WW 640

// Per-(b, class, row) stats. 16*6*368 = 35328 entries per array.
__device__ int g_rmin[BATCH * 6 * HH];
__device__ int g_rmax[BATCH * 6 * HH];
__device__ int g_rcnt[BATCH * 6 * HH];
__device__ float g_part[BATCH * 6];

// -------------------------------------------------------------------------
// Kernel 1: per-pixel class via soft-argmax, reduced per-row per-class to
// (min col, max col, count). One block per (row, batch); 160 threads,
// each owning 4 consecutive pixels (float4 loads per class plane).
// -------------------------------------------------------------------------
__device__ __forceinline__ int pix_class(const float l[7]) {
    float e0 = __expf(l[0]);
    float e1 = __expf(l[1]);
    float e2 = __expf(l[2]);
    float e3 = __expf(l[3]);
    float e4 = __expf(l[4]);
    float e5 = __expf(l[5]);
    float e6 = __expf(l[6]);
    float den = ((e0 + e1) + (e2 + e3)) + ((e4 + e5) + e6);
    float num = e1;
    num = fmaf(2.0f, e2, num);
    num = fmaf(3.0f, e3, num);
    num = fmaf(4.0f, e4, num);
    num = fmaf(5.0f, e5, num);
    num = fmaf(6.0f, e6, num);
    // floor(num/den) without MUFU RCP: staircase of compares (ALU pipe).
    int k = (num >= den);
    k += (num >= 2.0f * den);
    k += (num >= 3.0f * den);
    k += (num >= 4.0f * den);
    k += (num >= 5.0f * den);
    k += (num >= 6.0f * den);
    return k;
}

__global__ __launch_bounds__(160) void k_rowstats(const float* __restrict__ logits) {
    const int row  = blockIdx.x;
    const int b    = blockIdx.y;
    const int t    = threadIdx.x;
    const int lane = t & 31;
    const int warp = t >> 5;
    const int col0 = t << 2;   // 4 pixels per thread

    // Load 4 consecutive pixels from each of the 7 class planes.
    float4 v[NCLS];
#pragma unroll
    for (int c = 0; c < NCLS; c++) {
        const float* p = logits + (((size_t)b * NCLS + c) * HH + row) * WW + col0;
        v[c] = *reinterpret_cast<const float4*>(p);
    }

    int k[4];
    {
        float l[7];
#pragma unroll
        for (int c = 0; c < NCLS; c++) l[c] = v[c].x;
        k[0] = pix_class(l);
#pragma unroll
        for (int c = 0; c < NCLS; c++) l[c] = v[c].y;
        k[1] = pix_class(l);
#pragma unroll
        for (int c = 0; c < NCLS; c++) l[c] = v[c].z;
        k[2] = pix_class(l);
#pragma unroll
        for (int c = 0; c < NCLS; c++) l[c] = v[c].w;
        k[3] = pix_class(l);
    }

    // Warp-level per-class reduction via ballot. Warp covers cols
    // [warp*128, warp*128+128); pixel (lane, j) has col = 128*warp + 4*lane + j.
    const int warpbase = warp << 7;
    int mn[6], mx[6], ct[6];
#pragma unroll
    for (int c = 0; c < 6; c++) { mn[c] = 0x7fffffff; mx[c] = -1; ct[c] = 0; }

#pragma unroll
    for (int c = 1; c <= 6; c++) {
#pragma unroll
        for (int j = 0; j < 4; j++) {
            unsigned m = __ballot_sync(0xffffffffu, k[j] == c);
            ct[c - 1] += __popc(m);
            if (m) {  // uniform branch (ballot result is warp-uniform)
                int lo = __ffs(m) - 1;
                int hi = 31 - __clz(m);
                int cmin = warpbase + (lo << 2) + j;
                int cmax = warpbase + (hi << 2) + j;
                mn[c - 1] = min(mn[c - 1], cmin);
                mx[c - 1] = max(mx[c - 1], cmax);
            }
        }
    }

    // Cross-warp combine (5 warps) through shared memory.
    __shared__ int smn[5][6], smx[5][6], sct[5][6];
    if (lane == 0) {
#pragma unroll
        for (int c = 0; c < 6; c++) {
            smn[warp][c] = mn[c];
            smx[warp][c] = mx[c];
            sct[warp][c] = ct[c];
        }
    }
    __syncthreads();

    if (t < 6) {
        int fmn = 0x7fffffff, fmx = -1, fct = 0;
#pragma unroll
        for (int w = 0; w < 5; w++) {
            fmn = min(fmn, smn[w][t]);
            fmx = max(fmx, smx[w][t]);
            fct += sct[w][t];
        }
        const int idx = ((b * 6 + t) * HH) + row;
        g_rmin[idx] = fmn;
        g_rmax[idx] = fmx;
        g_rcnt[idx] = fct;
    }
}

// -------------------------------------------------------------------------
// Kernel 2: per (b, class) ordered combine across 368 rows.
// Within-row contribution telescopes to (max_col - min_col); cross-row
// transitions add |d_first(cur) - d_last(prev)| with d = col - row.
// One warp per (b, class): each lane scans 12 contiguous rows sequentially,
// then an ordered shuffle-tree merges lane segments.
// -------------------------------------------------------------------------
__global__ void k_combine() {
    const int id   = blockIdx.x;       // 0..95
    const int lane = threadIdx.x;      // 0..31
    const int base = id * HH;          // layout: [b][c][row]

    int valid = 0, cnt = 0, S = 0;
    int fcol = 0, frow = 0, lcol = 0, lrow = 0;

    const int r0 = lane * 12;
    const int r1 = min(HH, r0 + 12);
    for (int r = r0; r < r1; r++) {
        int c = g_rcnt[base + r];
        if (!c) continue;
        int mnv = g_rmin[base + r];
        int mxv = g_rmax[base + r];
        if (valid) {
            S += abs((mnv - r) - (lcol - lrow));
        } else {
            fcol = mnv; frow = r; valid = 1;
        }
        S += mxv - mnv;
        lcol = mxv; lrow = r; cnt += c;
    }

    // Ordered tree reduction: at step `off`, lanes that are multiples of
    // 2*off absorb the segment from lane+off (the segment to their right).
#pragma unroll
    for (int off = 1; off < 32; off <<= 1) {
        int ov  = __shfl_down_sync(0xffffffffu, valid, off);
        int oc  = __shfl_down_sync(0xffffffffu, cnt, off);
        int oS  = __shfl_down_sync(0xffffffffu, S, off);
        int ofc = __shfl_down_sync(0xffffffffu, fcol, off);
        int ofr = __shfl_down_sync(0xffffffffu, frow, off);
        int olc = __shfl_down_sync(0xffffffffu, lcol, off);
        int olr = __shfl_down_sync(0xffffffffu, lrow, off);
        if ((lane & (2 * off - 1)) == 0) {
            if (ov) {
                if (valid) {
                    S += oS + abs((ofc - ofr) - (lcol - lrow));
                } else {
                    S = oS; fcol = ofc; frow = ofr; valid = 1;
                }
                cnt += oc;
                lcol = olc; lrow = olr;
            }
        }
    }

    if (lane == 0) {
        float loss = 0.0f;
        if (cnt >= 2) {
            loss = ((float)S / (float)(cnt - 1)) / (float)(cnt + 1);
        }
        g_part[id] = loss;
    }
}

// -------------------------------------------------------------------------
// Kernel 3: deterministic sum of the 96 partials -> d_out[0].
// -------------------------------------------------------------------------
__global__ void k_final(float* __restrict__ out) {
    const int t = threadIdx.x;  // 128 threads
    float v = (t < BATCH * 6) ? g_part[t] : 0.0f;
#pragma unroll
    for (int off = 16; off > 0; off >>= 1)
        v += __shfl_down_sync(0xffffffffu, v, off);
    __shared__ float sh[4];
    if ((t & 31) == 0) sh[t >> 5] = v;
    __syncthreads();
    if (t == 0) {
        float s = (sh[0] + sh[1]) + (sh[2] + sh[3]);
        out[0] = s;
    }
}

extern "C" void kernel_launch(void* const* d_in, const int* in_sizes, int n_in,
                              void* d_out, int out_size) {
    const float* logits = (const float*)d_in[0];
    // d_in[1] (labels) is unused by the reference computation.
    dim3 g1(HH, BATCH);
    k_rowstats<<<g1, 160>>>(logits);
    k_combine<<<BATCH * 6, 32>>>();
    k_final<<<1, 128>>>((float*)d_out);
}

// round 2
// speedup vs baseline: 1.0022x; 1.0022x over previous
#include <cuda_runtime.h>
#include <cstdint>

#define BATCH 16
#define NCLS 7
#define HH 368
#define WW 640

// Packed per-(b, class, row) stats: bits[0:10)=min col, [10:20)=max col,
// [20:31)=count (0 means empty row for this class).
__device__ unsigned g_row[BATCH * 6 * HH];

// -------------------------------------------------------------------------
// Kernel 1: per-pixel class via soft-argmax -> per-row per-class
// (min col, max col, count). One block per (row, batch); 160 threads,
// 4 consecutive pixels each (float4 per class plane).
// -------------------------------------------------------------------------
__device__ __forceinline__ int pix_class(const float l[7]) {
    float e0 = __expf(l[0]);
    float e1 = __expf(l[1]);
    float e2 = __expf(l[2]);
    float e3 = __expf(l[3]);
    float e4 = __expf(l[4]);
    float e5 = __expf(l[5]);
    float e6 = __expf(l[6]);
    float den = ((e0 + e1) + (e2 + e3)) + ((e4 + e5) + e6);
    float num = e1;
    num = fmaf(2.0f, e2, num);
    num = fmaf(3.0f, e3, num);
    num = fmaf(4.0f, e4, num);
    num = fmaf(5.0f, e5, num);
    num = fmaf(6.0f, e6, num);
    // num/den in [0,6]; truncation == floor for non-negative values.
    float r = __fdividef(num, den);
    return (int)r;
}

__global__ __launch_bounds__(160) void k_rowstats(const float* __restrict__ logits) {
    const int row  = blockIdx.x;
    const int b    = blockIdx.y;
    const int t    = threadIdx.x;
    const int lane = t & 31;
    const int warp = t >> 5;
    const int col0 = t << 2;   // 4 pixels per thread

    float4 v[NCLS];
#pragma unroll
    for (int c = 0; c < NCLS; c++) {
        const float* p = logits + (((size_t)b * NCLS + c) * HH + row) * WW + col0;
        v[c] = *reinterpret_cast<const float4*>(p);
    }

    int k0, k1, k2, k3;
    {
        float l[7];
#pragma unroll
        for (int c = 0; c < NCLS; c++) l[c] = v[c].x;
        k0 = pix_class(l);
#pragma unroll
        for (int c = 0; c < NCLS; c++) l[c] = v[c].y;
        k1 = pix_class(l);
#pragma unroll
        for (int c = 0; c < NCLS; c++) l[c] = v[c].z;
        k2 = pix_class(l);
#pragma unroll
        for (int c = 0; c < NCLS; c++) l[c] = v[c].w;
        k3 = pix_class(l);
    }

    // One-hot bitboard: byte j holds (1 << class_of_pixel_j).
    const unsigned B = (1u << k0) | (1u << (k1 + 8)) | (1u << (k2 + 16)) | (1u << (k3 + 24));

    __shared__ int smn[5][6], smx[5][6], sct[5][6];

#pragma unroll
    for (int c = 1; c <= 6; c++) {
        unsigned m = (B >> c) & 0x01010101u;  // bit 8*j set iff pixel j is class c
        int cnt = __popc(m);
        int mnl = m ? col0 + ((__ffs(m) - 1) >> 3) : 0x7fffffff;
        int mxl = m ? col0 + ((31 - __clz(m)) >> 3) : -1;
        int wmn = __reduce_min_sync(0xffffffffu, mnl);
        int wmx = __reduce_max_sync(0xffffffffu, mxl);
        int wct = __reduce_add_sync(0xffffffffu, cnt);
        if (lane == 0) {
            smn[warp][c - 1] = wmn;
            smx[warp][c - 1] = wmx;
            sct[warp][c - 1] = wct;
        }
    }
    __syncthreads();

    if (t < 6) {
        int fmn = 0x7fffffff, fmx = -1, fct = 0;
#pragma unroll
        for (int w = 0; w < 5; w++) {
            fmn = min(fmn, smn[w][t]);
            fmx = max(fmx, smx[w][t]);
            fct += sct[w][t];
        }
        const int idx = ((b * 6 + t) * HH) + row;
        unsigned pk = (fct == 0) ? 0u
            : ((unsigned)fmn | ((unsigned)fmx << 10) | ((unsigned)fct << 20));
        g_row[idx] = pk;
    }
}

// -------------------------------------------------------------------------
// Kernel 2 (fused combine + final): one block, 32 warps. Warp w handles
// segments 3w..3w+2 (96 = 16 batches x 6 classes). Within-row contribution
// telescopes to (max_col - min_col); cross-row transitions add
// |d_first(cur) - d_last(prev)| with d = col - row. Lane scans 12 contiguous
// rows, ordered shuffle-tree merges lane segments, then block-reduce.
// -------------------------------------------------------------------------
__global__ __launch_bounds__(1024) void k_tail(float* __restrict__ out) {
    const int t    = threadIdx.x;
    const int lane = t & 31;
    const int w    = t >> 5;

    float acc = 0.0f;

#pragma unroll 1
    for (int s = 0; s < 3; s++) {
        const int base = (w * 3 + s) * HH;

        int valid = 0, cnt = 0, S = 0;
        int fcol = 0, frow = 0, lcol = 0, lrow = 0;

        const int r0 = lane * 12;
        const int r1 = min(HH, r0 + 12);
        for (int r = r0; r < r1; r++) {
            unsigned pk = g_row[base + r];
            int c = pk >> 20;
            if (!c) continue;
            int mnv = pk & 1023;
            int mxv = (pk >> 10) & 1023;
            if (valid) {
                S += abs((mnv - r) - (lcol - lrow));
            } else {
                fcol = mnv; frow = r; valid = 1;
            }
            S += mxv - mnv;
            lcol = mxv; lrow = r; cnt += c;
        }

        // Ordered tree reduction: lane absorbs segment from lane+off.
#pragma unroll
        for (int off = 1; off < 32; off <<= 1) {
            int ov  = __shfl_down_sync(0xffffffffu, valid, off);
            int oc  = __shfl_down_sync(0xffffffffu, cnt, off);
            int oS  = __shfl_down_sync(0xffffffffu, S, off);
            int ofc = __shfl_down_sync(0xffffffffu, fcol, off);
            int ofr = __shfl_down_sync(0xffffffffu, frow, off);
            int olc = __shfl_down_sync(0xffffffffu, lcol, off);
            int olr = __shfl_down_sync(0xffffffffu, lrow, off);
            if ((lane & (2 * off - 1)) == 0) {
                if (ov) {
                    if (valid) {
                        S += oS + abs((ofc - ofr) - (lcol - lrow));
                    } else {
                        S = oS; fcol = ofc; frow = ofr; valid = 1;
                    }
                    cnt += oc;
                    lcol = olc; lrow = olr;
                }
            }
        }

        if (lane == 0 && cnt >= 2) {
            acc += ((float)S / (float)(cnt - 1)) / (float)(cnt + 1);
        }
    }

    __shared__ float sh[32];
    if (lane == 0) sh[w] = acc;
    __syncthreads();
    if (w == 0) {
        float v = sh[lane];
#pragma unroll
        for (int off = 16; off > 0; off >>= 1)
            v += __shfl_down_sync(0xffffffffu, v, off);
        if (lane == 0) out[0] = v;
    }
}

extern "C" void kernel_launch(void* const* d_in, const int* in_sizes, int n_in,
                              void* d_out, int out_size) {
    const float* logits = (const float*)d_in[0];
    // d_in[1] (labels) is unused by the reference computation.
    dim3 g1(HH, BATCH);
    k_rowstats<<<g1, 160>>>(logits);
    k_tail<<<1, 1024>>>((float*)d_out);
}

// round 3
// speedup vs baseline: 1.1515x; 1.1490x over previous
#include <cuda_runtime.h>
#include <cstdint>

#define BATCH 16
#define NCLS 7
#define HH 368
#define WW 640
#define NSEG (BATCH * 6)

// Packed per-(b, class, row) stats: bits[0:10)=min col, [10:20)=max col,
// [20:31)=count (0 means empty row for this class).
__device__ unsigned g_row[NSEG * HH];
__device__ float g_part[NSEG];
__device__ int g_done = 0;

// -------------------------------------------------------------------------
// Kernel 1: per-pixel class via soft-argmax -> per-row per-class
// (min col, max col, count). One block per (row, batch); 160 threads,
// 4 consecutive pixels each (float4 per class plane).
// -------------------------------------------------------------------------
__device__ __forceinline__ int pix_class(const float l[7]) {
    float e0 = __expf(l[0]);
    float e1 = __expf(l[1]);
    float e2 = __expf(l[2]);
    float e3 = __expf(l[3]);
    float e4 = __expf(l[4]);
    float e5 = __expf(l[5]);
    float e6 = __expf(l[6]);
    float den = ((e0 + e1) + (e2 + e3)) + ((e4 + e5) + e6);
    float num = e1;
    num = fmaf(2.0f, e2, num);
    num = fmaf(3.0f, e3, num);
    num = fmaf(4.0f, e4, num);
    num = fmaf(5.0f, e5, num);
    num = fmaf(6.0f, e6, num);
    // num/den in [0,6]; truncation == floor for non-negative values.
    float r = __fdividef(num, den);
    return (int)r;
}

__global__ __launch_bounds__(160) void k_rowstats(const float* __restrict__ logits) {
    const int row  = blockIdx.x;
    const int b    = blockIdx.y;
    const int t    = threadIdx.x;
    const int lane = t & 31;
    const int warp = t >> 5;
    const int col0 = t << 2;   // 4 pixels per thread

    float4 v[NCLS];
#pragma unroll
    for (int c = 0; c < NCLS; c++) {
        const float* p = logits + (((size_t)b * NCLS + c) * HH + row) * WW + col0;
        v[c] = *reinterpret_cast<const float4*>(p);
    }

    int k0, k1, k2, k3;
    {
        float l[7];
#pragma unroll
        for (int c = 0; c < NCLS; c++) l[c] = v[c].x;
        k0 = pix_class(l);
#pragma unroll
        for (int c = 0; c < NCLS; c++) l[c] = v[c].y;
        k1 = pix_class(l);
#pragma unroll
        for (int c = 0; c < NCLS; c++) l[c] = v[c].z;
        k2 = pix_class(l);
#pragma unroll
        for (int c = 0; c < NCLS; c++) l[c] = v[c].w;
        k3 = pix_class(l);
    }

    // One-hot bitboard: byte j holds (1 << class_of_pixel_j).
    const unsigned B = (1u << k0) | (1u << (k1 + 8)) | (1u << (k2 + 16)) | (1u << (k3 + 24));

    __shared__ int smn[5][6], smx[5][6], sct[5][6];

#pragma unroll
    for (int c = 1; c <= 6; c++) {
        unsigned m = (B >> c) & 0x01010101u;  // bit 8*j set iff pixel j is class c
        int cnt = __popc(m);
        int mnl = m ? col0 + ((__ffs(m) - 1) >> 3) : 0x7fffffff;
        int mxl = m ? col0 + ((31 - __clz(m)) >> 3) : -1;
        int wmn = __reduce_min_sync(0xffffffffu, mnl);
        int wmx = __reduce_max_sync(0xffffffffu, mxl);
        int wct = __reduce_add_sync(0xffffffffu, cnt);
        if (lane == 0) {
            smn[warp][c - 1] = wmn;
            smx[warp][c - 1] = wmx;
            sct[warp][c - 1] = wct;
        }
    }
    __syncthreads();

    if (t < 6) {
        int fmn = 0x7fffffff, fmx = -1, fct = 0;
#pragma unroll
        for (int w = 0; w < 5; w++) {
            fmn = min(fmn, smn[w][t]);
            fmx = max(fmx, smx[w][t]);
            fct += sct[w][t];
        }
        const int idx = ((b * 6 + t) * HH) + row;
        unsigned pk = (fct == 0) ? 0u
            : ((unsigned)fmn | ((unsigned)fmx << 10) | ((unsigned)fct << 20));
        g_row[idx] = pk;
    }
}

// -------------------------------------------------------------------------
// Kernel 2: one block per segment (96 blocks, 384 threads). Thread r loads
// row r's packed stats; ordered merges: 5 shuffle steps within warp, then
// one cross-warp merge (12 warp results). The last block to finish sums the
// 96 partials (threadfence + counter) and writes the scalar.
// Segment merge: within-row contribution telescopes to (max-min); merging
// adjacent segments adds |d_first(right) - d_last(left)|, d = col - row.
// -------------------------------------------------------------------------
__global__ __launch_bounds__(384) void k_combine(float* __restrict__ out) {
    const int seg  = blockIdx.x;
    const int t    = threadIdx.x;
    const int lane = t & 31;
    const int w    = t >> 5;

    int valid = 0, cnt = 0, S = 0;
    int fcol = 0, frow = 0, lcol = 0, lrow = 0;

    if (t < HH) {
        unsigned pk = g_row[seg * HH + t];
        cnt = pk >> 20;
        if (cnt) {
            int mnv = pk & 1023;
            int mxv = (pk >> 10) & 1023;
            valid = 1;
            S = mxv - mnv;
            fcol = mnv; frow = t;
            lcol = mxv; lrow = t;
        }
    }

    // Ordered warp tree: lane absorbs the segment from lane+off (its right).
#pragma unroll
    for (int off = 1; off < 32; off <<= 1) {
        int ov  = __shfl_down_sync(0xffffffffu, valid, off);
        int oc  = __shfl_down_sync(0xffffffffu, cnt, off);
        int oS  = __shfl_down_sync(0xffffffffu, S, off);
        int ofc = __shfl_down_sync(0xffffffffu, fcol, off);
        int ofr = __shfl_down_sync(0xffffffffu, frow, off);
        int olc = __shfl_down_sync(0xffffffffu, lcol, off);
        int olr = __shfl_down_sync(0xffffffffu, lrow, off);
        if ((lane & (2 * off - 1)) == 0 && ov) {
            if (valid) {
                S += oS + abs((ofc - ofr) - (lcol - lrow));
            } else {
                S = oS; fcol = ofc; frow = ofr; valid = 1;
            }
            cnt += oc;
            lcol = olc; lrow = olr;
        }
    }

    __shared__ int sv[16], sc[16], sS[16], sfc[16], sfr[16], slc[16], slr[16];
    if (t < 16) sv[t] = 0;  // pad warps 12..15 as invalid
    __syncthreads();
    if (lane == 0) {
        sv[w] = valid; sc[w] = cnt; sS[w] = S;
        sfc[w] = fcol; sfr[w] = frow; slc[w] = lcol; slr[w] = lrow;
    }
    __syncthreads();

    if (w == 0) {
        if (lane < 16) {
            valid = sv[lane]; cnt = sc[lane]; S = sS[lane];
            fcol = sfc[lane]; frow = sfr[lane]; lcol = slc[lane]; lrow = slr[lane];
        } else {
            valid = 0; cnt = 0; S = 0; fcol = frow = lcol = lrow = 0;
        }
#pragma unroll
        for (int off = 1; off < 16; off <<= 1) {
            int ov  = __shfl_down_sync(0xffffffffu, valid, off);
            int oc  = __shfl_down_sync(0xffffffffu, cnt, off);
            int oS  = __shfl_down_sync(0xffffffffu, S, off);
            int ofc = __shfl_down_sync(0xffffffffu, fcol, off);
            int ofr = __shfl_down_sync(0xffffffffu, frow, off);
            int olc = __shfl_down_sync(0xffffffffu, lcol, off);
            int olr = __shfl_down_sync(0xffffffffu, lrow, off);
            if ((lane & (2 * off - 1)) == 0 && ov) {
                if (valid) {
                    S += oS + abs((ofc - ofr) - (lcol - lrow));
                } else {
                    S = oS; fcol = ofc; frow = ofr; valid = 1;
                }
                cnt += oc;
                lcol = olc; lrow = olr;
            }
        }
        if (lane == 0) {
            float loss = 0.0f;
            if (cnt >= 2) {
                loss = ((float)S / (float)(cnt - 1)) / (float)(cnt + 1);
            }
            g_part[seg] = loss;
        }
    }

    // Last block finalizes: deterministic (integer counter, fixed sum order).
    __shared__ int s_last;
    __threadfence();
    if (t == 0) {
        int old = atomicAdd(&g_done, 1);
        s_last = (old == NSEG - 1);
    }
    __syncthreads();

    if (s_last && w == 0) {
        float v = g_part[lane] + g_part[lane + 32] + g_part[lane + 64];
#pragma unroll
        for (int off = 16; off > 0; off >>= 1)
            v += __shfl_down_sync(0xffffffffu, v, off);
        if (lane == 0) {
            out[0] = v;
            g_done = 0;  // reset for next graph replay
        }
    }
}

extern "C" void kernel_launch(void* const* d_in, const int* in_sizes, int n_in,
                              void* d_out, int out_size) {
    const float* logits = (const float*)d_in[0];
    // d_in[1] (labels) is unused by the reference computation.
    dim3 g1(HH, BATCH);
    k_rowstats<<<g1, 160>>>(logits);
    k_combine<<<NSEG, 384>>>((float*)d_out);
}